// round 7
// baseline (speedup 1.0000x reference)
#include <cuda_runtime.h>
#include <math.h>

#define BB 8
#define RR 4096
#define CC 1024
#define NROW (BB * RR)

// Scratch (no allocations allowed): per-row magnitudes + per-batch thresholds.
__device__ float d_mags[NROW];
__device__ float d_thr[BB];

// Branch-free two-sum accumulate: s += t with running compensation c.
__device__ __forceinline__ void twosum_acc(float& s, float& c, float t) {
    float y  = s + t;
    float bp = y - s;
    c += (s - (y - bp)) + (t - bp);
    s = y;
}

// ---------------------------------------------------------------------------
// Kernel 1: per-row L2 magnitudes. One warp per row (1024 floats = 256 float4;
// 8 float4 per lane, coalesced). Compensated fp32 (Neumaier) accumulation +
// compensated shuffle tree: ~2^-45 relative error, far below the ~1.4e-5
// relative gap between adjacent order statistics of 4096 Gaussian norms, so
// the top-k boundary matches the jax fp32 reference. No fp64 in the hot path.
// ---------------------------------------------------------------------------
__global__ void norms_kernel(const float* __restrict__ w) {
    int gwarp = (blockIdx.x * blockDim.x + threadIdx.x) >> 5;
    int lane = threadIdx.x & 31;
    if (gwarp >= NROW) return;

    const float4* row = reinterpret_cast<const float4*>(w + (size_t)gwarp * CC);
    float s = 0.0f, c = 0.0f;
#pragma unroll
    for (int i = 0; i < 8; i++) {
        float4 v = row[lane + i * 32];
        twosum_acc(s, c, v.x * v.x);
        twosum_acc(s, c, v.y * v.y);
        twosum_acc(s, c, v.z * v.z);
        twosum_acc(s, c, v.w * v.w);
    }
    // Compensated cross-lane reduction.
#pragma unroll
    for (int off = 16; off > 0; off >>= 1) {
        float so = __shfl_down_sync(0xffffffffu, s, off);
        float co = __shfl_down_sync(0xffffffffu, c, off);
        float S  = s + so;
        float bp = S - s;
        float e  = (s - (S - bp)) + (so - bp);
        c = c + co + e;
        s = S;
    }
    if (lane == 0) d_mags[gwarp] = sqrtf(s + c);
}

// ---------------------------------------------------------------------------
// Kernel 2: one block per batch.
//   (a) fp64 dot(logits[b], score_w) + score_b -> fp32 sigmoid -> rows_to_keep
//       (8 blocks x 1024 fp64 ops total — negligible, off the hot path)
//   (b) radix-select the k-th largest magnitude (float bits of non-negative
//       floats are monotone as uint32). 4 passes x 8 bits over 4096 values.
//       Terminating by construction: at every pass the remaining k is <= the
//       count of values matching the prefix, so the digit scan always breaks.
// ---------------------------------------------------------------------------
__global__ void thr_kernel(const float* __restrict__ logits,
                           const float* __restrict__ score_w,
                           const float* __restrict__ score_b) {
    const int b = blockIdx.x;
    const int tid = threadIdx.x;  // 256 threads

    __shared__ double sdot[256];
    __shared__ unsigned hist[256];
    __shared__ unsigned sh_prefix;
    __shared__ int sh_k;

    // --- (a) score -> k ---
    double acc = 0.0;
    for (int j = tid; j < CC; j += 256)
        acc += (double)logits[b * CC + j] * (double)score_w[j];
    sdot[tid] = acc;
    __syncthreads();
#pragma unroll
    for (int s2 = 128; s2 > 0; s2 >>= 1) {
        if (tid < s2) sdot[tid] += sdot[tid + s2];
        __syncthreads();
    }
    if (tid == 0) {
        float s = (float)sdot[0] + score_b[0];
        float kf = 1.0f / (1.0f + expf(-s));           // fp32 sigmoid, like ref
        int k = (int)(kf * (float)RR);                  // fp32 mul + trunc, like ref
        if (k < 1) k = 1;
        if (k > RR) k = RR;
        sh_k = k;
    }
    __syncthreads();

    // --- (b) radix select k-th largest among d_mags[b*RR .. +RR) ---
    unsigned prefix = 0;
    int k = sh_k;
    const float* mags = d_mags + b * RR;

    for (int shift = 24; shift >= 0; shift -= 8) {
        hist[tid] = 0;
        __syncthreads();

        unsigned hi_mask = (shift == 24) ? 0u : (0xFFFFFFFFu << (shift + 8));
        for (int i = tid; i < RR; i += 256) {
            unsigned key = __float_as_uint(mags[i]);
            if ((key & hi_mask) == (prefix & hi_mask))
                atomicAdd(&hist[(key >> shift) & 0xFFu], 1u);
        }
        __syncthreads();

        if (tid == 0) {
            int cum = 0;
            for (int d = 255; d >= 0; d--) {
                cum += (int)hist[d];
                if (cum >= k) {
                    sh_prefix = prefix | ((unsigned)d << shift);
                    sh_k = k - (cum - (int)hist[d]);
                    break;
                }
            }
        }
        __syncthreads();
        prefix = sh_prefix;
        k = sh_k;
        __syncthreads();  // protect hist reuse next pass
    }

    if (tid == 0) d_thr[b] = __uint_as_float(prefix);
}

// ---------------------------------------------------------------------------
// Kernel 3: streaming mask-multiply, float4 in/out. Walks W in REVERSE block
// order: after the norms pass the tail of W is the freshest content in L2
// (126MB L2 vs 134MB W), so reverse traversal converts part of the second
// read from DRAM misses into L2 hits.
// ---------------------------------------------------------------------------
__global__ void mask_kernel(const float4* __restrict__ w, float4* __restrict__ out) {
    int bid = gridDim.x - 1 - blockIdx.x;               // reverse order
    int idx = bid * blockDim.x + threadIdx.x;           // float4 index
    int row = idx >> 8;                                 // 256 float4 per row
    int b = row >> 12;                                  // 4096 rows per batch
    float keep = (d_mags[row] >= d_thr[b]) ? 1.0f : 0.0f;
    float4 v = w[idx];
    v.x *= keep; v.y *= keep; v.z *= keep; v.w *= keep;
    out[idx] = v;
}

// ---------------------------------------------------------------------------
extern "C" void kernel_launch(void* const* d_in, const int* in_sizes, int n_in,
                              void* d_out, int out_size) {
    const float* w       = (const float*)d_in[0];  // [8,4096,1024] f32
    const float* logits  = (const float*)d_in[1];  // [8,1024] f32
    const float* score_w = (const float*)d_in[2];  // [1024,1] f32
    const float* score_b = (const float*)d_in[3];  // [1] f32

    (void)in_sizes; (void)n_in; (void)out_size;

    // 1 warp per row: 32768 warps -> 4096 blocks of 256 threads
    norms_kernel<<<4096, 256>>>(w);
    // one block per batch
    thr_kernel<<<BB, 256>>>(logits, score_w, score_b);
    // 8.39M float4 elements, 1 per thread
    mask_kernel<<<32768, 256>>>((const float4*)w, (float4*)d_out);
}

// round 8
// speedup vs baseline: 1.2717x; 1.2717x over previous
#include <cuda_runtime.h>
#include <math.h>

#define BB 8
#define RR 4096
#define CC 1024
#define NROW (BB * RR)

// Scratch (no allocations allowed): per-row magnitudes + per-batch thresholds.
__device__ float d_mags[NROW];
__device__ float d_thr[BB];

// Branch-free two-sum accumulate: s += t with running compensation c.
__device__ __forceinline__ void twosum_acc(float& s, float& c, float t) {
    float y  = s + t;
    float bp = y - s;
    c += (s - (y - bp)) + (t - bp);
    s = y;
}

// Compensated merge of two (s,c) pairs.
__device__ __forceinline__ void twosum_merge(float& s, float& c, float so, float co) {
    float S  = s + so;
    float bp = S - s;
    float e  = (s - (S - bp)) + (so - bp);
    c = c + co + e;
    s = S;
}

// ---------------------------------------------------------------------------
// Kernel 1: fused copy + per-row L2 magnitudes. One warp per row (256 float4;
// 8 float4 per lane, coalesced). Copies W verbatim to out (kept rows are
// already final; dropped rows get zeroed by kernel 3). Compensated fp32
// accumulation in 4 independent pairs (short dep chains) + compensated
// shuffle tree: ~2^-45 relative error, far below the ~1.4e-5 gap between
// adjacent order statistics, so the top-k boundary matches the jax reference.
// ---------------------------------------------------------------------------
__global__ void copy_norms_kernel(const float4* __restrict__ w,
                                  float4* __restrict__ out) {
    int gwarp = (blockIdx.x * blockDim.x + threadIdx.x) >> 5;
    int lane = threadIdx.x & 31;

    const float4* row = w + (size_t)gwarp * 256;
    float4* orow = out + (size_t)gwarp * 256;

    float s0 = 0.f, c0 = 0.f, s1 = 0.f, c1 = 0.f;
    float s2 = 0.f, c2 = 0.f, s3 = 0.f, c3 = 0.f;
#pragma unroll
    for (int i = 0; i < 8; i++) {
        float4 v = row[lane + i * 32];
        orow[lane + i * 32] = v;               // streaming copy
        twosum_acc(s0, c0, v.x * v.x);
        twosum_acc(s1, c1, v.y * v.y);
        twosum_acc(s2, c2, v.z * v.z);
        twosum_acc(s3, c3, v.w * v.w);
    }
    twosum_merge(s0, c0, s1, c1);
    twosum_merge(s2, c2, s3, c3);
    twosum_merge(s0, c0, s2, c2);

    // Compensated cross-lane reduction.
#pragma unroll
    for (int off = 16; off > 0; off >>= 1) {
        float so = __shfl_down_sync(0xffffffffu, s0, off);
        float co = __shfl_down_sync(0xffffffffu, c0, off);
        twosum_merge(s0, c0, so, co);
    }
    if (lane == 0) d_mags[gwarp] = sqrtf(s0 + c0);
}

// ---------------------------------------------------------------------------
// Kernel 2: one block per batch (256 threads).
//   (a) fp64 dot(logits[b], score_w) + score_b -> fp32 sigmoid -> k
//   (b) radix-select k-th largest magnitude. Two fixes vs the slow version:
//       - histogram fill uses __match_any_sync warp-aggregated smem atomics
//         (norms concentrate near 32.0, so early passes dump ~all 4096 values
//         into ONE bin; naive atomics would serialize ~4096 deep)
//       - the 256-bin "scan from top" is a parallel suffix-sum (8 double-
//         buffered steps) instead of a serial 256-iteration dependent chain.
// ---------------------------------------------------------------------------
__global__ void thr_kernel(const float* __restrict__ logits,
                           const float* __restrict__ score_w,
                           const float* __restrict__ score_b) {
    const int b = blockIdx.x;
    const int tid = threadIdx.x;  // 256 threads
    const int lane = tid & 31;

    __shared__ double sdot[256];
    __shared__ unsigned hist[256];
    __shared__ unsigned sufA[256];
    __shared__ unsigned sufB[256];
    __shared__ unsigned sh_prefix;
    __shared__ int sh_k;

    // --- (a) score -> k ---
    double acc = 0.0;
    for (int j = tid; j < CC; j += 256)
        acc += (double)logits[b * CC + j] * (double)score_w[j];
    sdot[tid] = acc;
    __syncthreads();
#pragma unroll
    for (int s2 = 128; s2 > 0; s2 >>= 1) {
        if (tid < s2) sdot[tid] += sdot[tid + s2];
        __syncthreads();
    }
    if (tid == 0) {
        float s = (float)sdot[0] + score_b[0];
        float kf = 1.0f / (1.0f + expf(-s));           // fp32 sigmoid, like ref
        int k = (int)(kf * (float)RR);                  // fp32 mul + trunc, like ref
        if (k < 1) k = 1;
        if (k > RR) k = RR;
        sh_k = k;
    }
    __syncthreads();

    // --- (b) radix select k-th largest among d_mags[b*RR .. +RR) ---
    unsigned prefix = 0;
    int k = sh_k;
    const float* mags = d_mags + b * RR;

    for (int shift = 24; shift >= 0; shift -= 8) {
        hist[tid] = 0;
        __syncthreads();

        unsigned hi_mask = (shift == 24) ? 0u : (0xFFFFFFFFu << (shift + 8));
#pragma unroll
        for (int i = 0; i < RR / 256; i++) {           // 16 values per thread
            unsigned key = __float_as_uint(mags[tid + i * 256]);
            // digit 0..255 if the value matches the prefix, else sentinel 256
            unsigned digit = ((key & hi_mask) == (prefix & hi_mask))
                                 ? ((key >> shift) & 0xFFu) : 256u;
            unsigned peers = __match_any_sync(0xffffffffu, digit);
            int leader = __ffs(peers) - 1;
            if (lane == leader && digit < 256u)
                atomicAdd(&hist[digit], (unsigned)__popc(peers));
        }
        __syncthreads();

        // Parallel suffix sum: suf[d] = sum_{j >= d} hist[j]
        unsigned v = hist[tid];
        sufA[tid] = v;
        __syncthreads();
        unsigned* src = sufA;
        unsigned* dst = sufB;
#pragma unroll
        for (int off = 1; off < 256; off <<= 1) {
            unsigned add = (tid + off < 256) ? src[tid + off] : 0u;
            dst[tid] = src[tid] + add;
            __syncthreads();
            unsigned* t = src; src = dst; dst = t;
        }
        // Select: largest d with suf[d] >= k  (exists: count(prefix) >= k invariant)
        unsigned mycum = src[tid];
        unsigned nextcum = (tid == 255) ? 0u : src[tid + 1];
        if (mycum >= (unsigned)k && nextcum < (unsigned)k) {
            sh_prefix = prefix | ((unsigned)tid << shift);
            sh_k = k - (int)nextcum;
        }
        __syncthreads();
        prefix = sh_prefix;
        k = sh_k;
        __syncthreads();
    }

    if (tid == 0) d_thr[b] = __uint_as_float(prefix);
}

// ---------------------------------------------------------------------------
// Kernel 3: write-only zeroing of dropped rows. One warp per row; kept rows
// exit immediately (no traffic). Dropped rows: 256 float4 zero stores.
// Expected traffic ~= drop_fraction * 134MB.
// ---------------------------------------------------------------------------
__global__ void zero_kernel(float4* __restrict__ out) {
    int gwarp = (blockIdx.x * blockDim.x + threadIdx.x) >> 5;
    int lane = threadIdx.x & 31;
    int b = gwarp >> 12;                               // 4096 rows per batch

    if (d_mags[gwarp] >= d_thr[b]) return;             // kept: already correct

    float4* orow = out + (size_t)gwarp * 256;
    const float4 z = make_float4(0.f, 0.f, 0.f, 0.f);
#pragma unroll
    for (int i = 0; i < 8; i++)
        orow[lane + i * 32] = z;
}

// ---------------------------------------------------------------------------
extern "C" void kernel_launch(void* const* d_in, const int* in_sizes, int n_in,
                              void* d_out, int out_size) {
    const float* w       = (const float*)d_in[0];  // [8,4096,1024] f32
    const float* logits  = (const float*)d_in[1];  // [8,1024] f32
    const float* score_w = (const float*)d_in[2];  // [1024,1] f32
    const float* score_b = (const float*)d_in[3];  // [1] f32

    (void)in_sizes; (void)n_in; (void)out_size;

    // 32768 rows, 1 warp per row -> 4096 blocks of 256 threads
    copy_norms_kernel<<<4096, 256>>>((const float4*)w, (float4*)d_out);
    // one block per batch
    thr_kernel<<<BB, 256>>>(logits, score_w, score_b);
    // zero the dropped rows only
    zero_kernel<<<4096, 256>>>((float4*)d_out);
}